// round 7
// baseline (speedup 1.0000x reference)
#include <cuda_runtime.h>
#include <cuda_bf16.h>
#include <cstdint>

#define N_NODES 10000
#define N_EDGES 320000
#define M_PAD 10112           // 79 * 128
#define BITMAP_WORDS 3125000  // ceil(10000*10000/32)

// ---------------- scratch (static device globals; no allocation) ----------------
__device__ unsigned int g_bitmap[BITMAP_WORDS];   // zero-initialized; invariant: zero between calls
__device__ float g_deg[N_NODES];
__device__ float g_h1[N_NODES * 256];
__device__ float g_h2[N_NODES * 256];
__device__ float g_psum[79 * 256];
__device__ float g_psum2[79 * 256];
__device__ float g_mean[256];
__device__ float g_rstd[256];
__device__ int g_is64;
// bf16-split activations, zero-padded rows to M_PAD (padding stays zero forever)
__device__ __nv_bfloat16 g_xh[M_PAD * 512];
__device__ __nv_bfloat16 g_xl[M_PAD * 512];
__device__ __nv_bfloat16 g_a1h[M_PAD * 256];
__device__ __nv_bfloat16 g_a1l[M_PAD * 256];
__device__ __nv_bfloat16 g_a2h[M_PAD * 256];
__device__ __nv_bfloat16 g_a2l[M_PAD * 256];
__device__ __nv_bfloat16 g_a3h[M_PAD * 128];
__device__ __nv_bfloat16 g_a3l[M_PAD * 128];
// transposed + bf16-split weights, zero-padded: [Npad][KP]
__device__ __nv_bfloat16 g_wth0[256 * 512];
__device__ __nv_bfloat16 g_wtl0[256 * 512];
__device__ __nv_bfloat16 g_wth1[256 * 256];
__device__ __nv_bfloat16 g_wtl1[256 * 256];
__device__ __nv_bfloat16 g_wth2[128 * 256];
__device__ __nv_bfloat16 g_wtl2[128 * 256];
__device__ __nv_bfloat16 g_wth3[128 * 128];
__device__ __nv_bfloat16 g_wtl3[128 * 128];

// ---------------- helpers ----------------
__device__ __forceinline__ uint32_t s2u(const void* p) {
    uint32_t a;
    asm("{ .reg .u64 t; cvta.to.shared.u64 t, %1; cvt.u32.u64 %0, t; }" : "=r"(a) : "l"(p));
    return a;
}

__device__ __forceinline__ void bsplit(float v, unsigned short& h, unsigned short& l) {
    __nv_bfloat16 hb = __float2bfloat16(v);
    float r = v - __bfloat162float(hb);
    __nv_bfloat16 lb = __float2bfloat16(r);
    h = __bfloat16_as_ushort(hb);
    l = __bfloat16_as_ushort(lb);
}

#define LDX4(r, addr) \
    asm volatile("ldmatrix.sync.aligned.m8n8.x4.shared.b16 {%0,%1,%2,%3}, [%4];" \
                 : "=r"((r)[0]), "=r"((r)[1]), "=r"((r)[2]), "=r"((r)[3]) : "r"(addr))

#define MMA(d, a, b0, b1) \
    asm volatile("mma.sync.aligned.m16n8k16.row.col.f32.bf16.bf16.f32 " \
                 "{%0,%1,%2,%3}, {%4,%5,%6,%7}, {%8,%9}, {%0,%1,%2,%3};" \
                 : "+f"((d)[0]), "+f"((d)[1]), "+f"((d)[2]), "+f"((d)[3]) \
                 : "r"((a)[0]), "r"((a)[1]), "r"((a)[2]), "r"((a)[3]), "r"(b0), "r"(b1))

#define CP_ASYNC16(dst, src) \
    asm volatile("cp.async.cg.shared.global [%0], [%1], 16;" :: "r"(dst), "l"(src))

// ---------------- init: detect dtype, deg = 1 ----------------
__global__ void init_deg_kernel(const unsigned int* __restrict__ w) {
    int i = blockIdx.x * blockDim.x + threadIdx.x;
    if (blockIdx.x == 0 && threadIdx.x < 32) {
        unsigned bad = (w[2 * threadIdx.x + 1] != 0u) ? 1u : 0u;
        unsigned m = __ballot_sync(0xffffffffu, bad);
        if (threadIdx.x == 0) g_is64 = (m == 0) ? 1 : 0;
    }
    if (i < N_NODES) g_deg[i] = 1.0f;
}

// ---------------- degree with dedup (set semantics) ----------------
__global__ void deg_kernel(const void* __restrict__ ei_raw) {
    int e = blockIdx.x * blockDim.x + threadIdx.x;
    if (e >= N_EDGES) return;
    int s, d;
    if (g_is64) {
        const long long* p = (const long long*)ei_raw;
        s = (int)p[e];
        d = (int)p[e + N_EDGES];
    } else {
        const int* p = (const int*)ei_raw;
        s = p[e];
        d = p[e + N_EDGES];
    }
    if ((unsigned)s >= N_NODES || (unsigned)d >= N_NODES) return;
    if (s == d) return;  // diagonal already 1 via eye()
    unsigned long long bit = (unsigned long long)s * N_NODES + (unsigned long long)d;
    unsigned int mask = 1u << ((unsigned)bit & 31u);
    unsigned int old = atomicOr(&g_bitmap[bit >> 5], mask);
    if (!(old & mask)) atomicAdd(&g_deg[s], 1.0f);
}

// ---------------- cleanup: restore bitmap==0 invariant (only touched words) ----------------
__global__ void bitmap_clean_kernel(const void* __restrict__ ei_raw) {
    int e = blockIdx.x * blockDim.x + threadIdx.x;
    if (e >= N_EDGES) return;
    int s, d;
    if (g_is64) {
        const long long* p = (const long long*)ei_raw;
        s = (int)p[e];
        d = (int)p[e + N_EDGES];
    } else {
        const int* p = (const int*)ei_raw;
        s = p[e];
        d = p[e + N_EDGES];
    }
    if ((unsigned)s >= N_NODES || (unsigned)d >= N_NODES) return;
    if (s == d) return;
    unsigned long long bit = (unsigned long long)s * N_NODES + (unsigned long long)d;
    g_bitmap[bit >> 5] = 0u;
}

// -------- merged weight transpose + bf16 split (4 segments, one launch) --------
struct TSeg {
    const float* W;
    __nv_bfloat16 *th, *tl;
    int K, KP, N, Npad;
};

__global__ void transpose_split4(TSeg s0, TSeg s1, TSeg s2, TSeg s3) {
    TSeg s = (blockIdx.z == 0) ? s0 : (blockIdx.z == 1) ? s1 : (blockIdx.z == 2) ? s2 : s3;
    int k0 = blockIdx.x * 32, n0 = blockIdx.y * 32;
    if (k0 >= s.KP || n0 >= s.Npad) return;
    __shared__ float t[32][33];
    for (int dy = threadIdx.y; dy < 32; dy += 8) {
        int k = k0 + dy, n = n0 + threadIdx.x;
        t[dy][threadIdx.x] = (k < s.K && n < s.N) ? s.W[(size_t)k * s.N + n] : 0.f;
    }
    __syncthreads();
    for (int dy = threadIdx.y; dy < 32; dy += 8) {
        int n = n0 + dy, k = k0 + threadIdx.x;
        if (n < s.Npad && k < s.KP) {
            unsigned short h, l;
            bsplit(t[threadIdx.x][dy], h, l);
            s.th[(size_t)n * s.KP + k] = __ushort_as_bfloat16(h);
            s.tl[(size_t)n * s.KP + k] = __ushort_as_bfloat16(l);
        }
    }
}

// -------- split fp32 activation into bf16 hi/lo, K zero-padded ----
__global__ void split_act(const float* __restrict__ X,
                          __nv_bfloat16* __restrict__ oh, __nv_bfloat16* __restrict__ ol,
                          int M, int K, int KP) {
    int idx = blockIdx.x * blockDim.x + threadIdx.x;
    int n4 = KP >> 2;
    if (idx >= M * n4) return;
    int row = idx / n4, c4 = (idx % n4) * 4;
    float v[4] = {0.f, 0.f, 0.f, 0.f};
    if (c4 + 3 < K) {
        float4 f = *(const float4*)&X[(size_t)row * K + c4];
        v[0] = f.x; v[1] = f.y; v[2] = f.z; v[3] = f.w;
    } else {
#pragma unroll
        for (int j = 0; j < 4; j++)
            if (c4 + j < K) v[j] = X[(size_t)row * K + c4 + j];
    }
    unsigned short h[4], l[4];
#pragma unroll
    for (int j = 0; j < 4; j++) bsplit(v[j], h[j], l[j]);
    *(uint2*)&oh[(size_t)row * KP + c4] =
        make_uint2((uint32_t)h[0] | ((uint32_t)h[1] << 16), (uint32_t)h[2] | ((uint32_t)h[3] << 16));
    *(uint2*)&ol[(size_t)row * KP + c4] =
        make_uint2((uint32_t)l[0] | ((uint32_t)l[1] << 16), (uint32_t)l[2] | ((uint32_t)l[3] << 16));
}

// ---------------- mma.sync bf16-split GEMM, cp.async 3-stage pipeline ----------------
// CTA 128x128, 8 warps (4x2) of 32x64 warp tiles, BK=32.
// OUTM 0: fp32 C. OUTM 2: bf16 hi/lo split out.
// STATS: emit per-CTA column sums/sumsq of output into psum/psum2 [79][256] (disjoint slots).
// rs: optional per-row scale applied in epilogue (deg fold for conv0): v = relu(rs*acc + bias).
#define ROWB 80
#define AH_OFF 0
#define AL_OFF 10240
#define BH_OFF 20480
#define BL_OFF 30720
#define BUF_SZ 40960
#define STAGES 3
#define SMEM_DYN (STAGES * BUF_SZ + 1024)

template <int OUTM, bool STATS>
__global__ void __launch_bounds__(256, 1)
gemm_mma(const __nv_bfloat16* __restrict__ Ah, const __nv_bfloat16* __restrict__ Al,
         const __nv_bfloat16* __restrict__ Bh, const __nv_bfloat16* __restrict__ Bl,
         const float* __restrict__ bias, const float* __restrict__ rs,
         float* __restrict__ Cf, __nv_bfloat16* __restrict__ Ch, __nv_bfloat16* __restrict__ Cl,
         int M, int Kpad, int Ncols) {
    extern __shared__ char smraw[];
    uint32_t raw = s2u(smraw);
    uint32_t sbase = (raw + 1023u) & ~1023u;
    char* sb = smraw + (sbase - raw);

    const int tid = threadIdx.x, lane = tid & 31, wid = tid >> 5;
    const int row0 = blockIdx.y * 128, col0 = blockIdx.x * 128;
    const int wm = (wid >> 1) * 32, wn = (wid & 1) * 64;
    const int nch = Kpad >> 5;

    float acc[2][8][4];
#pragma unroll
    for (int i = 0; i < 2; i++)
#pragma unroll
        for (int j = 0; j < 8; j++)
#pragma unroll
            for (int c = 0; c < 4; c++) acc[i][j][c] = 0.f;

    const uint32_t a_lo = (uint32_t)((lane & 15) * ROWB + ((lane >> 4) & 1) * 16);
    const uint32_t b_lo = (uint32_t)((lane & 7) * ROWB + ((lane & 16) ? 8 * ROWB : 0) +
                                     ((lane & 8) ? 16 : 0));

    auto prefetch = [&](int ch) {
        const int buf = ch % STAGES;
        const uint32_t bu = sbase + buf * BUF_SZ;
        const int k0 = ch << 5;
#pragma unroll
        for (int t = 0; t < 2; t++) {
            int idx = tid + t * 256;
            int r = idx >> 2, q = idx & 3;
            size_t ao = (size_t)(row0 + r) * Kpad + k0 + q * 8;
            size_t bo = (size_t)(col0 + r) * Kpad + k0 + q * 8;
            uint32_t so = (uint32_t)(r * ROWB + q * 16);
            CP_ASYNC16(bu + AH_OFF + so, (const void*)(Ah + ao));
            CP_ASYNC16(bu + AL_OFF + so, (const void*)(Al + ao));
            CP_ASYNC16(bu + BH_OFF + so, (const void*)(Bh + bo));
            CP_ASYNC16(bu + BL_OFF + so, (const void*)(Bl + bo));
        }
        asm volatile("cp.async.commit_group;" ::: "memory");
    };

    prefetch(0);
    prefetch(1);

    for (int ch = 0; ch < nch; ch++) {
        asm volatile("cp.async.wait_group 1;" ::: "memory");
        __syncthreads();
        if (ch + 2 < nch) prefetch(ch + 2);

        const uint32_t bufu = sbase + (ch % STAGES) * BUF_SZ;
#pragma unroll
        for (int ks = 0; ks < 2; ks++) {
            uint32_t ka = bufu + AH_OFF + (uint32_t)(wm * ROWB) + a_lo + ks * 32;
            uint32_t ah0[4], ah1[4], al0[4], al1[4];
            LDX4(ah0, ka);
            LDX4(ah1, ka + 16 * ROWB);
            LDX4(al0, ka + (AL_OFF - AH_OFF));
            LDX4(al1, ka + (AL_OFF - AH_OFF) + 16 * ROWB);
#pragma unroll
            for (int nt = 0; nt < 4; nt++) {
                uint32_t kb = bufu + BH_OFF + (uint32_t)((wn + nt * 16) * ROWB) + b_lo + ks * 32;
                uint32_t bh[4], bl[4];
                LDX4(bh, kb);
                LDX4(bl, kb + (BL_OFF - BH_OFF));
                MMA(acc[0][nt * 2 + 0], ah0, bh[0], bh[1]);
                MMA(acc[1][nt * 2 + 0], ah1, bh[0], bh[1]);
                MMA(acc[0][nt * 2 + 1], ah0, bh[2], bh[3]);
                MMA(acc[1][nt * 2 + 1], ah1, bh[2], bh[3]);
                MMA(acc[0][nt * 2 + 0], al0, bh[0], bh[1]);
                MMA(acc[1][nt * 2 + 0], al1, bh[0], bh[1]);
                MMA(acc[0][nt * 2 + 1], al0, bh[2], bh[3]);
                MMA(acc[1][nt * 2 + 1], al1, bh[2], bh[3]);
                MMA(acc[0][nt * 2 + 0], ah0, bl[0], bl[1]);
                MMA(acc[1][nt * 2 + 0], ah1, bl[0], bl[1]);
                MMA(acc[0][nt * 2 + 1], ah0, bl[2], bl[3]);
                MMA(acc[1][nt * 2 + 1], ah1, bl[2], bl[3]);
            }
        }
        __syncthreads();
    }

    // epilogue: v = relu(rs*acc + bias); stores + optional fused column stats
    float ts[8][2], ts2[8][2];
    if (STATS) {
#pragma unroll
        for (int j = 0; j < 8; j++) { ts[j][0] = ts[j][1] = ts2[j][0] = ts2[j][1] = 0.f; }
    }
#pragma unroll
    for (int mi = 0; mi < 2; mi++) {
        int r0_ = row0 + wm + mi * 16 + (lane >> 2);
        bool ok0 = r0_ < M, ok1 = (r0_ + 8) < M;
        float d0 = 1.f, d1 = 1.f;
        if (rs) {
            if (ok0) d0 = rs[r0_];
            if (ok1) d1 = rs[r0_ + 8];
        }
#pragma unroll
        for (int n8 = 0; n8 < 8; n8++) {
            int gc = col0 + wn + n8 * 8 + (lane & 3) * 2;
            if (gc >= Ncols) continue;
            float bv0 = bias[gc], bv1 = bias[gc + 1];
            float v0 = d0 * acc[mi][n8][0] + bv0; v0 = v0 > 0.f ? v0 : 0.f;
            float v1 = d0 * acc[mi][n8][1] + bv1; v1 = v1 > 0.f ? v1 : 0.f;
            float v2 = d1 * acc[mi][n8][2] + bv0; v2 = v2 > 0.f ? v2 : 0.f;
            float v3 = d1 * acc[mi][n8][3] + bv1; v3 = v3 > 0.f ? v3 : 0.f;
            if (STATS) {
                if (ok0) { ts[n8][0] += v0; ts2[n8][0] += v0 * v0;
                           ts[n8][1] += v1; ts2[n8][1] += v1 * v1; }
                if (ok1) { ts[n8][0] += v2; ts2[n8][0] += v2 * v2;
                           ts[n8][1] += v3; ts2[n8][1] += v3 * v3; }
            }
            if (OUTM == 0) {
                if (ok0) *(float2*)&Cf[(size_t)r0_ * Ncols + gc] = make_float2(v0, v1);
                if (ok1) *(float2*)&Cf[(size_t)(r0_ + 8) * Ncols + gc] = make_float2(v2, v3);
            } else {
                unsigned short h0, h1, h2, h3, l0, l1, l2, l3;
                bsplit(v0, h0, l0); bsplit(v1, h1, l1);
                bsplit(v2, h2, l2); bsplit(v3, h3, l3);
                if (ok0) {
                    *(uint32_t*)&Ch[(size_t)r0_ * Ncols + gc] = (uint32_t)h0 | ((uint32_t)h1 << 16);
                    *(uint32_t*)&Cl[(size_t)r0_ * Ncols + gc] = (uint32_t)l0 | ((uint32_t)l1 << 16);
                }
                if (ok1) {
                    *(uint32_t*)&Ch[(size_t)(r0_ + 8) * Ncols + gc] = (uint32_t)h2 | ((uint32_t)h3 << 16);
                    *(uint32_t*)&Cl[(size_t)(r0_ + 8) * Ncols + gc] = (uint32_t)l2 | ((uint32_t)l3 << 16);
                }
            }
        }
    }

    if (STATS) {
        // reduce across the 8 row-lane-groups within the warp (lanes differing in bits 2..4)
#pragma unroll
        for (int n8 = 0; n8 < 8; n8++)
#pragma unroll
            for (int k = 0; k < 2; k++) {
#pragma unroll
                for (int off = 4; off < 32; off <<= 1) {
                    ts[n8][k] += __shfl_xor_sync(0xffffffffu, ts[n8][k], off);
                    ts2[n8][k] += __shfl_xor_sync(0xffffffffu, ts2[n8][k], off);
                }
            }
        // smem: sS[8 warps][64 cols], sS2 same (reuse pipeline buffers)
        float* sS = (float*)sb;
        float* sS2 = sS + 8 * 64;
        __syncthreads();
        if (lane < 4) {
#pragma unroll
            for (int n8 = 0; n8 < 8; n8++) {
                int cloc = n8 * 8 + lane * 2;
                sS[wid * 64 + cloc] = ts[n8][0];
                sS[wid * 64 + cloc + 1] = ts[n8][1];
                sS2[wid * 64 + cloc] = ts2[n8][0];
                sS2[wid * 64 + cloc + 1] = ts2[n8][1];
            }
        }
        __syncthreads();
        if (tid < 128) {
            int c = tid;                 // 0..127 within CTA tile
            int half = c >> 6, cloc = c & 63;
            float s = 0.f, s2 = 0.f;
#pragma unroll
            for (int w = 0; w < 4; w++) {
                s += sS[(half + 2 * w) * 64 + cloc];
                s2 += sS2[(half + 2 * w) * 64 + cloc];
            }
            g_psum[blockIdx.y * 256 + col0 + c] = s;
            g_psum2[blockIdx.y * 256 + col0 + c] = s2;
        }
    }
}

// ---------------- BN finalize: mean/rstd from 79 partials ----------------
__global__ void bn_finalize(int nrb, int N, int M) {
    int c = blockIdx.x * blockDim.x + threadIdx.x;
    if (c >= N) return;
    float s = 0.f, s2 = 0.f;
    for (int b = 0; b < nrb; b++) { s += g_psum[b * N + c]; s2 += g_psum2[b * N + c]; }
    float m = s / (float)M;
    float var = s2 / (float)M - m * m;
    g_mean[c] = m;
    g_rstd[c] = rsqrtf(var + 1e-5f);
}

// -------- BN apply: fp32 in -> bf16 hi/lo split out (optional row-scale fold) --------
__global__ void bn_apply_split(const float* __restrict__ H, const float* __restrict__ g,
                               const float* __restrict__ b, const float* __restrict__ rs,
                               __nv_bfloat16* __restrict__ oh, __nv_bfloat16* __restrict__ ol,
                               int M, int N) {
    int idx = blockIdx.x * blockDim.x + threadIdx.x;
    int n4 = N >> 2;
    if (idx >= M * n4) return;
    int row = idx / n4, c4 = (idx % n4) * 4;
    float4 h = *(const float4*)&H[(size_t)row * N + c4];
    float r = rs ? rs[row] : 1.f;
    float* hp = &h.x;
    unsigned short hh[4], ll[4];
#pragma unroll
    for (int j = 0; j < 4; j++) {
        int c = c4 + j;
        float v = ((hp[j] - g_mean[c]) * g_rstd[c] * g[c] + b[c]) * r;
        bsplit(v, hh[j], ll[j]);
    }
    *(uint2*)&oh[(size_t)row * N + c4] =
        make_uint2((uint32_t)hh[0] | ((uint32_t)hh[1] << 16), (uint32_t)hh[2] | ((uint32_t)hh[3] << 16));
    *(uint2*)&ol[(size_t)row * N + c4] =
        make_uint2((uint32_t)ll[0] | ((uint32_t)ll[1] << 16), (uint32_t)ll[2] | ((uint32_t)ll[3] << 16));
}

// ---------------- launch ----------------
extern "C" void kernel_launch(void* const* d_in, const int* in_sizes, int n_in,
                              void* d_out, int out_size) {
    const float* x   = (const float*)d_in[0];
    const void*  ei  = d_in[1];
    const float* W0  = (const float*)d_in[2];
    const float* b0  = (const float*)d_in[3];
    const float* g0  = (const float*)d_in[4];
    const float* be0 = (const float*)d_in[5];
    const float* W1  = (const float*)d_in[6];
    const float* b1  = (const float*)d_in[7];
    const float* g1  = (const float*)d_in[8];
    const float* be1 = (const float*)d_in[9];
    const float* fW0 = (const float*)d_in[10];
    const float* fb0 = (const float*)d_in[11];
    const float* fW1 = (const float*)d_in[12];
    const float* fb1 = (const float*)d_in[13];
    float* out = (float*)d_out;

    float *deg, *h1, *h2;
    __nv_bfloat16 *xh, *xl, *a1h, *a1l, *a2h, *a2l, *a3h, *a3l;
    __nv_bfloat16 *wth0, *wtl0, *wth1, *wtl1, *wth2, *wtl2, *wth3, *wtl3;
    cudaGetSymbolAddress((void**)&deg, g_deg);
    cudaGetSymbolAddress((void**)&h1, g_h1);
    cudaGetSymbolAddress((void**)&h2, g_h2);
    cudaGetSymbolAddress((void**)&xh, g_xh);
    cudaGetSymbolAddress((void**)&xl, g_xl);
    cudaGetSymbolAddress((void**)&a1h, g_a1h);
    cudaGetSymbolAddress((void**)&a1l, g_a1l);
    cudaGetSymbolAddress((void**)&a2h, g_a2h);
    cudaGetSymbolAddress((void**)&a2l, g_a2l);
    cudaGetSymbolAddress((void**)&a3h, g_a3h);
    cudaGetSymbolAddress((void**)&a3l, g_a3l);
    cudaGetSymbolAddress((void**)&wth0, g_wth0);
    cudaGetSymbolAddress((void**)&wtl0, g_wtl0);
    cudaGetSymbolAddress((void**)&wth1, g_wth1);
    cudaGetSymbolAddress((void**)&wtl1, g_wtl1);
    cudaGetSymbolAddress((void**)&wth2, g_wth2);
    cudaGetSymbolAddress((void**)&wtl2, g_wtl2);
    cudaGetSymbolAddress((void**)&wth3, g_wth3);
    cudaGetSymbolAddress((void**)&wtl3, g_wtl3);

    cudaFuncSetAttribute((const void*)gemm_mma<0, true>, cudaFuncAttributeMaxDynamicSharedMemorySize, SMEM_DYN);
    cudaFuncSetAttribute((const void*)gemm_mma<0, false>, cudaFuncAttributeMaxDynamicSharedMemorySize, SMEM_DYN);
    cudaFuncSetAttribute((const void*)gemm_mma<2, false>, cudaFuncAttributeMaxDynamicSharedMemorySize, SMEM_DYN);

    const int M = N_NODES;
    dim3 tb(32, 8);

    // weight prep (one launch) + input split (deg-independent)
    TSeg s0 = {W0, wth0, wtl0, 500, 512, 256, 256};
    TSeg s1 = {W1, wth1, wtl1, 256, 256, 256, 256};
    TSeg s2 = {fW0, wth2, wtl2, 256, 256, 128, 128};
    TSeg s3 = {fW1, wth3, wtl3, 128, 128, 40, 128};
    transpose_split4<<<dim3(16, 8, 4), tb>>>(s0, s1, s2, s3);
    split_act<<<(M * 128 + 255) / 256, 256>>>(x, xh, xl, M, 500, 512);

    // degree (bitmap is all-zero by invariant; cleanup restores it)
    init_deg_kernel<<<(N_NODES + 255) / 256, 256>>>((const unsigned int*)ei);
    deg_kernel<<<(N_EDGES + 255) / 256, 256>>>(ei);
    bitmap_clean_kernel<<<(N_EDGES + 255) / 256, 256>>>(ei);

    // conv0: h1 = relu(deg .* (x@W0) + b0), stats fused; apply folds deg for conv1
    gemm_mma<0, true><<<dim3(2, 79), 256, SMEM_DYN>>>(xh, xl, wth0, wtl0, b0, deg, h1,
                                                      nullptr, nullptr, M, 512, 256);
    bn_finalize<<<1, 256>>>(79, 256, M);
    bn_apply_split<<<(M * 64 + 255) / 256, 256>>>(h1, g0, be0, deg, a1h, a1l, M, 256);

    // conv1: h2 = relu(a1 @ W1 + b1), stats fused
    gemm_mma<0, true><<<dim3(2, 79), 256, SMEM_DYN>>>(a1h, a1l, wth1, wtl1, b1, nullptr, h2,
                                                      nullptr, nullptr, M, 256, 256);
    bn_finalize<<<1, 256>>>(79, 256, M);
    bn_apply_split<<<(M * 64 + 255) / 256, 256>>>(h2, g1, be1, nullptr, a2h, a2l, M, 256);

    // fc0: split bf16 output directly for fc1
    gemm_mma<2, false><<<dim3(1, 79), 256, SMEM_DYN>>>(a2h, a2l, wth2, wtl2, fb0, nullptr,
                                                       nullptr, a3h, a3l, M, 256, 128);
    // fc1: fp32 out [10000][40]
    gemm_mma<0, false><<<dim3(1, 79), 256, SMEM_DYN>>>(a3h, a3l, wth3, wtl3, fb1, nullptr,
                                                       out, nullptr, nullptr, M, 128, 40);
}

// round 8
// speedup vs baseline: 1.1237x; 1.1237x over previous
#include <cuda_runtime.h>
#include <cuda_bf16.h>
#include <cstdint>

#define N_NODES 10000
#define N_EDGES 320000
#define M_PAD 10112           // 79 * 128
#define BITMAP_WORDS 3125000  // ceil(10000*10000/32)

// ---------------- scratch (static device globals; no allocation) ----------------
__device__ unsigned int g_bitmap[BITMAP_WORDS];
__device__ float g_deg[N_NODES];
__device__ float g_h1[N_NODES * 256];
__device__ float g_h2[N_NODES * 256];
__device__ float g_psum[79 * 256];
__device__ float g_psum2[79 * 256];
__device__ float g_mean[256];
__device__ float g_rstd[256];
__device__ int g_is64;
// bf16-split activations, zero-padded rows to M_PAD (padding stays zero forever)
__device__ __nv_bfloat16 g_xh[M_PAD * 512];
__device__ __nv_bfloat16 g_xl[M_PAD * 512];
__device__ __nv_bfloat16 g_a1h[M_PAD * 256];
__device__ __nv_bfloat16 g_a1l[M_PAD * 256];
__device__ __nv_bfloat16 g_a2h[M_PAD * 256];
__device__ __nv_bfloat16 g_a2l[M_PAD * 256];
// transposed + bf16-split weights, zero-padded: [Npad][KP]
__device__ __nv_bfloat16 g_wth0[256 * 512];
__device__ __nv_bfloat16 g_wtl0[256 * 512];
__device__ __nv_bfloat16 g_wth1[256 * 256];
__device__ __nv_bfloat16 g_wtl1[256 * 256];
__device__ __nv_bfloat16 g_wth2[128 * 256];
__device__ __nv_bfloat16 g_wtl2[128 * 256];
__device__ __nv_bfloat16 g_wth3[128 * 128];
__device__ __nv_bfloat16 g_wtl3[128 * 128];

// ---------------- helpers ----------------
__device__ __forceinline__ uint32_t s2u(const void* p) {
    uint32_t a;
    asm("{ .reg .u64 t; cvta.to.shared.u64 t, %1; cvt.u32.u64 %0, t; }" : "=r"(a) : "l"(p));
    return a;
}

__device__ __forceinline__ void bsplit(float v, unsigned short& h, unsigned short& l) {
    __nv_bfloat16 hb = __float2bfloat16(v);
    float r = v - __bfloat162float(hb);
    __nv_bfloat16 lb = __float2bfloat16(r);
    h = __bfloat16_as_ushort(hb);
    l = __bfloat16_as_ushort(lb);
}

#define LDX4(r, addr) \
    asm volatile("ldmatrix.sync.aligned.m8n8.x4.shared.b16 {%0,%1,%2,%3}, [%4];" \
                 : "=r"((r)[0]), "=r"((r)[1]), "=r"((r)[2]), "=r"((r)[3]) : "r"(addr))

#define MMA(d, a, b0, b1) \
    asm volatile("mma.sync.aligned.m16n8k16.row.col.f32.bf16.bf16.f32 " \
                 "{%0,%1,%2,%3}, {%4,%5,%6,%7}, {%8,%9}, {%0,%1,%2,%3};" \
                 : "+f"((d)[0]), "+f"((d)[1]), "+f"((d)[2]), "+f"((d)[3]) \
                 : "r"((a)[0]), "r"((a)[1]), "r"((a)[2]), "r"((a)[3]), "r"(b0), "r"(b1))

#define CP_ASYNC16(dst, src) \
    asm volatile("cp.async.cg.shared.global [%0], [%1], 16;" :: "r"(dst), "l"(src))

// ---------------- init: streaming bitmap memset + deg=1 + dtype detect ----------------
__global__ void init_kernel(const unsigned int* __restrict__ w) {
    int i = blockIdx.x * blockDim.x + threadIdx.x;
    if (blockIdx.x == 0 && threadIdx.x < 32) {
        unsigned bad = (w[2 * threadIdx.x + 1] != 0u) ? 1u : 0u;
        unsigned m = __ballot_sync(0xffffffffu, bad);
        if (threadIdx.x == 0) g_is64 = (m == 0) ? 1 : 0;
    }
    if (i < BITMAP_WORDS / 4 + 1) {
        uint4 z = {0u, 0u, 0u, 0u};
        if (4 * i + 3 < BITMAP_WORDS) *(uint4*)&g_bitmap[4 * i] = z;
        else for (int j = 4 * i; j < BITMAP_WORDS; j++) g_bitmap[j] = 0u;
    }
    if (i < N_NODES) g_deg[i] = 1.0f;
}

// ---------------- degree with dedup (set semantics), 2 edges/thread ----------------
__global__ void deg_kernel(const void* __restrict__ ei_raw) {
    int t = blockIdx.x * blockDim.x + threadIdx.x;
    const int half = N_EDGES / 2;
    if (t >= half) return;
    const int is64 = g_is64;
#pragma unroll
    for (int u = 0; u < 2; u++) {
        int e = t + u * half;
        int s, d;
        if (is64) {
            const long long* p = (const long long*)ei_raw;
            s = (int)p[e];
            d = (int)p[e + N_EDGES];
        } else {
            const int* p = (const int*)ei_raw;
            s = p[e];
            d = p[e + N_EDGES];
        }
        if ((unsigned)s >= N_NODES || (unsigned)d >= N_NODES) continue;
        if (s == d) continue;  // diagonal already 1 via eye()
        unsigned long long bit = (unsigned long long)s * N_NODES + (unsigned long long)d;
        unsigned int mask = 1u << ((unsigned)bit & 31u);
        unsigned int old = atomicOr(&g_bitmap[bit >> 5], mask);
        if (!(old & mask)) atomicAdd(&g_deg[s], 1.0f);
    }
}

// -------- merged weight transpose + bf16 split (4 segments, one launch) --------
struct TSeg {
    const float* W;
    __nv_bfloat16 *th, *tl;
    int K, KP, N, Npad;
};

__global__ void transpose_split4(TSeg s0, TSeg s1, TSeg s2, TSeg s3) {
    TSeg s = (blockIdx.z == 0) ? s0 : (blockIdx.z == 1) ? s1 : (blockIdx.z == 2) ? s2 : s3;
    int k0 = blockIdx.x * 32, n0 = blockIdx.y * 32;
    if (k0 >= s.KP || n0 >= s.Npad) return;
    __shared__ float t[32][33];
    for (int dy = threadIdx.y; dy < 32; dy += 8) {
        int k = k0 + dy, n = n0 + threadIdx.x;
        t[dy][threadIdx.x] = (k < s.K && n < s.N) ? s.W[(size_t)k * s.N + n] : 0.f;
    }
    __syncthreads();
    for (int dy = threadIdx.y; dy < 32; dy += 8) {
        int n = n0 + dy, k = k0 + threadIdx.x;
        if (n < s.Npad && k < s.KP) {
            unsigned short h, l;
            bsplit(t[threadIdx.x][dy], h, l);
            s.th[(size_t)n * s.KP + k] = __ushort_as_bfloat16(h);
            s.tl[(size_t)n * s.KP + k] = __ushort_as_bfloat16(l);
        }
    }
}

// -------- split fp32 activation into bf16 hi/lo, K zero-padded ----
__global__ void split_act(const float* __restrict__ X,
                          __nv_bfloat16* __restrict__ oh, __nv_bfloat16* __restrict__ ol,
                          int M, int K, int KP) {
    int idx = blockIdx.x * blockDim.x + threadIdx.x;
    int n4 = KP >> 2;
    if (idx >= M * n4) return;
    int row = idx / n4, c4 = (idx % n4) * 4;
    float v[4] = {0.f, 0.f, 0.f, 0.f};
    if (c4 + 3 < K) {
        float4 f = *(const float4*)&X[(size_t)row * K + c4];
        v[0] = f.x; v[1] = f.y; v[2] = f.z; v[3] = f.w;
    } else {
#pragma unroll
        for (int j = 0; j < 4; j++)
            if (c4 + j < K) v[j] = X[(size_t)row * K + c4 + j];
    }
    unsigned short h[4], l[4];
#pragma unroll
    for (int j = 0; j < 4; j++) bsplit(v[j], h[j], l[j]);
    *(uint2*)&oh[(size_t)row * KP + c4] =
        make_uint2((uint32_t)h[0] | ((uint32_t)h[1] << 16), (uint32_t)h[2] | ((uint32_t)h[3] << 16));
    *(uint2*)&ol[(size_t)row * KP + c4] =
        make_uint2((uint32_t)l[0] | ((uint32_t)l[1] << 16), (uint32_t)l[2] | ((uint32_t)l[3] << 16));
}

// ---------------- mma.sync bf16-split GEMM, cp.async 3-stage pipeline ----------------
// CTA 128x128, 8 warps (4x2) of 32x64 warp tiles, BK=32. fp32 out + fused column stats.
// rs: optional per-row scale applied in epilogue: v = relu(rs*acc + bias).
#define ROWB 80
#define AH_OFF 0
#define AL_OFF 10240
#define BH_OFF 20480
#define BL_OFF 30720
#define BUF_SZ 40960
#define STAGES 3
#define SMEM_DYN (STAGES * BUF_SZ + 1024)

__global__ void __launch_bounds__(256, 1)
gemm_mma(const __nv_bfloat16* __restrict__ Ah, const __nv_bfloat16* __restrict__ Al,
         const __nv_bfloat16* __restrict__ Bh, const __nv_bfloat16* __restrict__ Bl,
         const float* __restrict__ bias, const float* __restrict__ rs,
         float* __restrict__ Cf, int M, int Kpad, int Ncols) {
    extern __shared__ char smraw[];
    uint32_t raw = s2u(smraw);
    uint32_t sbase = (raw + 1023u) & ~1023u;
    char* sb = smraw + (sbase - raw);

    const int tid = threadIdx.x, lane = tid & 31, wid = tid >> 5;
    const int row0 = blockIdx.y * 128, col0 = blockIdx.x * 128;
    const int wm = (wid >> 1) * 32, wn = (wid & 1) * 64;
    const int nch = Kpad >> 5;

    float acc[2][8][4];
#pragma unroll
    for (int i = 0; i < 2; i++)
#pragma unroll
        for (int j = 0; j < 8; j++)
#pragma unroll
            for (int c = 0; c < 4; c++) acc[i][j][c] = 0.f;

    const uint32_t a_lo = (uint32_t)((lane & 15) * ROWB + ((lane >> 4) & 1) * 16);
    const uint32_t b_lo = (uint32_t)((lane & 7) * ROWB + ((lane & 16) ? 8 * ROWB : 0) +
                                     ((lane & 8) ? 16 : 0));

    auto prefetch = [&](int ch) {
        const int buf = ch % STAGES;
        const uint32_t bu = sbase + buf * BUF_SZ;
        const int k0 = ch << 5;
#pragma unroll
        for (int t = 0; t < 2; t++) {
            int idx = tid + t * 256;
            int r = idx >> 2, q = idx & 3;
            size_t ao = (size_t)(row0 + r) * Kpad + k0 + q * 8;
            size_t bo = (size_t)(col0 + r) * Kpad + k0 + q * 8;
            uint32_t so = (uint32_t)(r * ROWB + q * 16);
            CP_ASYNC16(bu + AH_OFF + so, (const void*)(Ah + ao));
            CP_ASYNC16(bu + AL_OFF + so, (const void*)(Al + ao));
            CP_ASYNC16(bu + BH_OFF + so, (const void*)(Bh + bo));
            CP_ASYNC16(bu + BL_OFF + so, (const void*)(Bl + bo));
        }
        asm volatile("cp.async.commit_group;" ::: "memory");
    };

    prefetch(0);
    prefetch(1);

    for (int ch = 0; ch < nch; ch++) {
        asm volatile("cp.async.wait_group 1;" ::: "memory");
        __syncthreads();
        if (ch + 2 < nch) prefetch(ch + 2);

        const uint32_t bufu = sbase + (ch % STAGES) * BUF_SZ;
#pragma unroll
        for (int ks = 0; ks < 2; ks++) {
            uint32_t ka = bufu + AH_OFF + (uint32_t)(wm * ROWB) + a_lo + ks * 32;
            uint32_t ah0[4], ah1[4], al0[4], al1[4];
            LDX4(ah0, ka);
            LDX4(ah1, ka + 16 * ROWB);
            LDX4(al0, ka + (AL_OFF - AH_OFF));
            LDX4(al1, ka + (AL_OFF - AH_OFF) + 16 * ROWB);
#pragma unroll
            for (int nt = 0; nt < 4; nt++) {
                uint32_t kb = bufu + BH_OFF + (uint32_t)((wn + nt * 16) * ROWB) + b_lo + ks * 32;
                uint32_t bh[4], bl[4];
                LDX4(bh, kb);
                LDX4(bl, kb + (BL_OFF - BH_OFF));
                MMA(acc[0][nt * 2 + 0], ah0, bh[0], bh[1]);
                MMA(acc[1][nt * 2 + 0], ah1, bh[0], bh[1]);
                MMA(acc[0][nt * 2 + 1], ah0, bh[2], bh[3]);
                MMA(acc[1][nt * 2 + 1], ah1, bh[2], bh[3]);
                MMA(acc[0][nt * 2 + 0], al0, bh[0], bh[1]);
                MMA(acc[1][nt * 2 + 0], al1, bh[0], bh[1]);
                MMA(acc[0][nt * 2 + 1], al0, bh[2], bh[3]);
                MMA(acc[1][nt * 2 + 1], al1, bh[2], bh[3]);
                MMA(acc[0][nt * 2 + 0], ah0, bl[0], bl[1]);
                MMA(acc[1][nt * 2 + 0], ah1, bl[0], bl[1]);
                MMA(acc[0][nt * 2 + 1], ah0, bl[2], bl[3]);
                MMA(acc[1][nt * 2 + 1], ah1, bl[2], bl[3]);
            }
        }
        __syncthreads();
    }

    // epilogue: v = relu(rs*acc + bias); stores + fused column stats
    float ts[8][2], ts2[8][2];
#pragma unroll
    for (int j = 0; j < 8; j++) { ts[j][0] = ts[j][1] = ts2[j][0] = ts2[j][1] = 0.f; }
#pragma unroll
    for (int mi = 0; mi < 2; mi++) {
        int r0_ = row0 + wm + mi * 16 + (lane >> 2);
        bool ok0 = r0_ < M, ok1 = (r0_ + 8) < M;
        float d0 = 1.f, d1 = 1.f;
        if (rs) {
            if (ok0) d0 = rs[r0_];
            if (ok1) d1 = rs[r0_ + 8];
        }
#pragma unroll
        for (int n8 = 0; n8 < 8; n8++) {
            int gc = col0 + wn + n8 * 8 + (lane & 3) * 2;
            float bv0 = bias[gc], bv1 = bias[gc + 1];
            float v0 = d0 * acc[mi][n8][0] + bv0; v0 = v0 > 0.f ? v0 : 0.f;
            float v1 = d0 * acc[mi][n8][1] + bv1; v1 = v1 > 0.f ? v1 : 0.f;
            float v2 = d1 * acc[mi][n8][2] + bv0; v2 = v2 > 0.f ? v2 : 0.f;
            float v3 = d1 * acc[mi][n8][3] + bv1; v3 = v3 > 0.f ? v3 : 0.f;
            if (ok0) { ts[n8][0] += v0; ts2[n8][0] += v0 * v0;
                       ts[n8][1] += v1; ts2[n8][1] += v1 * v1; }
            if (ok1) { ts[n8][0] += v2; ts2[n8][0] += v2 * v2;
                       ts[n8][1] += v3; ts2[n8][1] += v3 * v3; }
            if (ok0) *(float2*)&Cf[(size_t)r0_ * Ncols + gc] = make_float2(v0, v1);
            if (ok1) *(float2*)&Cf[(size_t)(r0_ + 8) * Ncols + gc] = make_float2(v2, v3);
        }
    }

    // reduce across the 8 row-lane-groups within the warp
#pragma unroll
    for (int n8 = 0; n8 < 8; n8++)
#pragma unroll
        for (int k = 0; k < 2; k++) {
#pragma unroll
            for (int off = 4; off < 32; off <<= 1) {
                ts[n8][k] += __shfl_xor_sync(0xffffffffu, ts[n8][k], off);
                ts2[n8][k] += __shfl_xor_sync(0xffffffffu, ts2[n8][k], off);
            }
        }
    float* sS = (float*)sb;
    float* sS2 = sS + 8 * 64;
    __syncthreads();
    if (lane < 4) {
#pragma unroll
        for (int n8 = 0; n8 < 8; n8++) {
            int cloc = n8 * 8 + lane * 2;
            sS[wid * 64 + cloc] = ts[n8][0];
            sS[wid * 64 + cloc + 1] = ts[n8][1];
            sS2[wid * 64 + cloc] = ts2[n8][0];
            sS2[wid * 64 + cloc + 1] = ts2[n8][1];
        }
    }
    __syncthreads();
    if (tid < 128) {
        int c = tid;
        int half = c >> 6, cloc = c & 63;
        float s = 0.f, s2 = 0.f;
#pragma unroll
        for (int w = 0; w < 4; w++) {
            s += sS[(half + 2 * w) * 64 + cloc];
            s2 += sS2[(half + 2 * w) * 64 + cloc];
        }
        g_psum[blockIdx.y * 256 + col0 + c] = s;
        g_psum2[blockIdx.y * 256 + col0 + c] = s2;
    }
}

// ---------------- fused fc0+fc1: out = relu(relu(a2@W2+b2) @ W3 + b3) ----------------
// Stage 1: standard pipeline GEMM (K=256, N=128), epilogue -> bf16 split in SMEM.
// Stage 2: smem-resident GEMM (K=128, N=40), direct fp32 out.
// SMEM reuse after stage-1 mainloop: SA (4 chunks x hi/lo, 81920 B) + SB (fc1 W, 40960 B).
__global__ void __launch_bounds__(256, 1)
fused_fc(const __nv_bfloat16* __restrict__ Ah, const __nv_bfloat16* __restrict__ Al,
         const __nv_bfloat16* __restrict__ Bh, const __nv_bfloat16* __restrict__ Bl,
         const float* __restrict__ bias0,
         const __nv_bfloat16* __restrict__ W3h, const __nv_bfloat16* __restrict__ W3l,
         const float* __restrict__ bias1, float* __restrict__ Out, int M) {
    extern __shared__ char smraw[];
    uint32_t raw = s2u(smraw);
    uint32_t sbase = (raw + 1023u) & ~1023u;

    const int tid = threadIdx.x, lane = tid & 31, wid = tid >> 5;
    const int row0 = blockIdx.y * 128;
    const int wm = (wid >> 1) * 32, wn = (wid & 1) * 64;
    const int Kpad = 256, nch = 8;

    float acc[2][8][4];
#pragma unroll
    for (int i = 0; i < 2; i++)
#pragma unroll
        for (int j = 0; j < 8; j++)
#pragma unroll
            for (int c = 0; c < 4; c++) acc[i][j][c] = 0.f;

    const uint32_t a_lo = (uint32_t)((lane & 15) * ROWB + ((lane >> 4) & 1) * 16);
    const uint32_t b_lo = (uint32_t)((lane & 7) * ROWB + ((lane & 16) ? 8 * ROWB : 0) +
                                     ((lane & 8) ? 16 : 0));

    auto prefetch = [&](int ch) {
        const int buf = ch % STAGES;
        const uint32_t bu = sbase + buf * BUF_SZ;
        const int k0 = ch << 5;
#pragma unroll
        for (int t = 0; t < 2; t++) {
            int idx = tid + t * 256;
            int r = idx >> 2, q = idx & 3;
            size_t ao = (size_t)(row0 + r) * Kpad + k0 + q * 8;
            size_t bo = (size_t)r * Kpad + k0 + q * 8;
            uint32_t so = (uint32_t)(r * ROWB + q * 16);
            CP_ASYNC16(bu + AH_OFF + so, (const void*)(Ah + ao));
            CP_ASYNC16(bu + AL_OFF + so, (const void*)(Al + ao));
            CP_ASYNC16(bu + BH_OFF + so, (const void*)(Bh + bo));
            CP_ASYNC16(bu + BL_OFF + so, (const void*)(Bl + bo));
        }
        asm volatile("cp.async.commit_group;" ::: "memory");
    };

    prefetch(0);
    prefetch(1);

    for (int ch = 0; ch < nch; ch++) {
        asm volatile("cp.async.wait_group 1;" ::: "memory");
        __syncthreads();
        if (ch + 2 < nch) prefetch(ch + 2);

        const uint32_t bufu = sbase + (ch % STAGES) * BUF_SZ;
#pragma unroll
        for (int ks = 0; ks < 2; ks++) {
            uint32_t ka = bufu + AH_OFF + (uint32_t)(wm * ROWB) + a_lo + ks * 32;
            uint32_t ah0[4], ah1[4], al0[4], al1[4];
            LDX4(ah0, ka);
            LDX4(ah1, ka + 16 * ROWB);
            LDX4(al0, ka + (AL_OFF - AH_OFF));
            LDX4(al1, ka + (AL_OFF - AH_OFF) + 16 * ROWB);
#pragma unroll
            for (int nt = 0; nt < 4; nt++) {
                uint32_t kb = bufu + BH_OFF + (uint32_t)((wn + nt * 16) * ROWB) + b_lo + ks * 32;
                uint32_t bh[4], bl[4];
                LDX4(bh, kb);
                LDX4(bl, kb + (BL_OFF - BH_OFF));
                MMA(acc[0][nt * 2 + 0], ah0, bh[0], bh[1]);
                MMA(acc[1][nt * 2 + 0], ah1, bh[0], bh[1]);
                MMA(acc[0][nt * 2 + 1], ah0, bh[2], bh[3]);
                MMA(acc[1][nt * 2 + 1], ah1, bh[2], bh[3]);
                MMA(acc[0][nt * 2 + 0], al0, bh[0], bh[1]);
                MMA(acc[1][nt * 2 + 0], al1, bh[0], bh[1]);
                MMA(acc[0][nt * 2 + 1], al0, bh[2], bh[3]);
                MMA(acc[1][nt * 2 + 1], al1, bh[2], bh[3]);
                MMA(acc[0][nt * 2 + 0], ah0, bl[0], bl[1]);
                MMA(acc[1][nt * 2 + 0], ah1, bl[0], bl[1]);
                MMA(acc[0][nt * 2 + 1], ah0, bl[2], bl[3]);
                MMA(acc[1][nt * 2 + 1], ah1, bl[2], bl[3]);
            }
        }
        __syncthreads();
    }
    __syncthreads();  // stage-1 buffers now free

    // SA: per k-chunk c (of fc1 K=128): hi at c*20480, lo at +10240 (rows 128 x ROWB)
    // SB: fc1 weights at 81920 + c*10240 (hi) / +5120 (lo): 64 n-rows x ROWB
    const uint32_t SA = sbase;
    const uint32_t SB = sbase + 81920;

    // load fc1 weights (64 rows cover N=40 + zero pad) via cp.async
#pragma unroll
    for (int t = 0; t < 4; t++) {
        int idx = tid + t * 256;          // 0..1023: c(2b)|r(6b)|q(2b)
        int c = idx >> 8, r = (idx >> 2) & 63, q = idx & 3;
        size_t go = (size_t)r * 128 + c * 32 + q * 8;
        uint32_t so = SB + c * 10240 + (uint32_t)(r * ROWB + q * 16);
        CP_ASYNC16(so, (const void*)(W3h + go));
        CP_ASYNC16(so + 5120, (const void*)(W3l + go));
    }
    asm volatile("cp.async.commit_group;" ::: "memory");

    // stage-1 epilogue: relu(acc+bias0) -> bf16 split into SA (chunked layout)
    char* sac = smraw + (sbase - raw);
#pragma unroll
    for (int mi = 0; mi < 2; mi++) {
        int rl = wm + mi * 16 + (lane >> 2);     // CTA-local row
#pragma unroll
        for (int n8 = 0; n8 < 8; n8++) {
            int cl = wn + n8 * 8 + (lane & 3) * 2;   // fc0 output col == fc1 k index
            float bv0 = bias0[cl], bv1 = bias0[cl + 1];
            float v0 = acc[mi][n8][0] + bv0; v0 = v0 > 0.f ? v0 : 0.f;
            float v1 = acc[mi][n8][1] + bv1; v1 = v1 > 0.f ? v1 : 0.f;
            float v2 = acc[mi][n8][2] + bv0; v2 = v2 > 0.f ? v2 : 0.f;
            float v3 = acc[mi][n8][3] + bv1; v3 = v3 > 0.f ? v3 : 0.f;
            unsigned short h0, h1, h2, h3, l0, l1, l2, l3;
            bsplit(v0, h0, l0); bsplit(v1, h1, l1);
            bsplit(v2, h2, l2); bsplit(v3, h3, l3);
            uint32_t off = (uint32_t)((cl >> 5) * 20480 + rl * ROWB + (cl & 31) * 2);
            *(uint32_t*)(sac + off) = (uint32_t)h0 | ((uint32_t)h1 << 16);
            *(uint32_t*)(sac + off + 10240) = (uint32_t)l0 | ((uint32_t)l1 << 16);
            uint32_t off8 = off + 8 * ROWB;
            *(uint32_t*)(sac + off8) = (uint32_t)h2 | ((uint32_t)h3 << 16);
            *(uint32_t*)(sac + off8 + 10240) = (uint32_t)l2 | ((uint32_t)l3 << 16);
        }
    }
    asm volatile("cp.async.wait_group 0;" ::: "memory");
    __syncthreads();

    // stage 2: each warp computes rows [wid*16, wid*16+16) x cols 0..63 (N=40 used)
    float acc2[8][4];
#pragma unroll
    for (int j = 0; j < 8; j++)
#pragma unroll
        for (int c = 0; c < 4; c++) acc2[j][c] = 0.f;

#pragma unroll
    for (int c = 0; c < 4; c++) {
#pragma unroll
        for (int ks = 0; ks < 2; ks++) {
            uint32_t ka = SA + c * 20480 + (uint32_t)(wid * 16 * ROWB) + a_lo + ks * 32;
            uint32_t ah[4], al[4];
            LDX4(ah, ka);
            LDX4(al, ka + 10240);
#pragma unroll
            for (int nt = 0; nt < 4; nt++) {
                uint32_t kb = SB + c * 10240 + (uint32_t)(nt * 16 * ROWB) + b_lo + ks * 32;
                uint32_t bh[4], bl[4];
                LDX4(bh, kb);
                LDX4(bl, kb + 5120);
                MMA(acc2[nt * 2 + 0], ah, bh[0], bh[1]);
                MMA(acc2[nt * 2 + 1], ah, bh[2], bh[3]);
                MMA(acc2[nt * 2 + 0], al, bh[0], bh[1]);
                MMA(acc2[nt * 2 + 1], al, bh[2], bh[3]);
                MMA(acc2[nt * 2 + 0], ah, bl[0], bl[1]);
                MMA(acc2[nt * 2 + 1], ah, bl[2], bl[3]);
            }
        }
    }

    // stage-2 epilogue: relu(acc2 + bias1) -> Out [M][40]
#pragma unroll
    for (int nt = 0; nt < 4; nt++)
#pragma unroll
        for (int h = 0; h < 2; h++) {
            int gc = nt * 16 + h * 8 + (lane & 3) * 2;
            if (gc >= 40) continue;
            float bv0 = bias1[gc], bv1 = bias1[gc + 1];
            int gr = row0 + wid * 16 + (lane >> 2);
            float* a2 = acc2[nt * 2 + h];
            if (gr < M) {
                float v0 = a2[0] + bv0; v0 = v0 > 0.f ? v0 : 0.f;
                float v1 = a2[1] + bv1; v1 = v1 > 0.f ? v1 : 0.f;
                *(float2*)&Out[(size_t)gr * 40 + gc] = make_float2(v0, v1);
            }
            if (gr + 8 < M) {
                float v2 = a2[2] + bv0; v2 = v2 > 0.f ? v2 : 0.f;
                float v3 = a2[3] + bv1; v3 = v3 > 0.f ? v3 : 0.f;
                *(float2*)&Out[(size_t)(gr + 8) * 40 + gc] = make_float2(v2, v3);
            }
        }
}

// ---------------- BN finalize: mean/rstd from 79 partials ----------------
__global__ void bn_finalize(int nrb, int N, int M) {
    int c = blockIdx.x * blockDim.x + threadIdx.x;
    if (c >= N) return;
    float s = 0.f, s2 = 0.f;
    for (int b = 0; b < nrb; b++) { s += g_psum[b * N + c]; s2 += g_psum2[b * N + c]; }
    float m = s / (float)M;
    float var = s2 / (float)M - m * m;
    g_mean[c] = m;
    g_rstd[c] = rsqrtf(var + 1e-5f);
}

// -------- BN apply: fp32 in -> bf16 hi/lo split out (optional row-scale fold) --------
__global__ void bn_apply_split(const float* __restrict__ H, const float* __restrict__ g,
                               const float* __restrict__ b, const float* __restrict__ rs,
                               __nv_bfloat16* __restrict__ oh, __nv_bfloat16* __restrict__ ol,
                               int M, int N) {
    int idx = blockIdx.x * blockDim.x + threadIdx.x;
    int n4 = N >> 2;
    if (idx >= M * n4) return;
    int row = idx / n4, c4 = (idx % n4) * 4;
    float4 h = *(const float4*)&H[(size_t)row * N + c4];
    float r = rs ? rs[row] : 1.f;
    float* hp = &h.x;
    unsigned short hh[4], ll[4];
#pragma unroll
    for (int j = 0; j < 4; j++) {
        int c = c4 + j;
        float v = ((hp[j] - g_mean[c]) * g_rstd[c] * g[c] + b[c]) * r;
        bsplit(v, hh[j], ll[j]);
    }
    *(uint2*)&oh[(size_t)row * N + c4] =
        make_uint2((uint32_t)hh[0] | ((uint32_t)hh[1] << 16), (uint32_t)hh[2] | ((uint32_t)hh[3] << 16));
    *(uint2*)&ol[(size_t)row * N + c4] =
        make_uint2((uint32_t)ll[0] | ((uint32_t)ll[1] << 16), (uint32_t)ll[2] | ((uint32_t)ll[3] << 16));
}

// ---------------- launch ----------------
extern "C" void kernel_launch(void* const* d_in, const int* in_sizes, int n_in,
                              void* d_out, int out_size) {
    const float* x   = (const float*)d_in[0];
    const void*  ei  = d_in[1];
    const float* W0  = (const float*)d_in[2];
    const float* b0  = (const float*)d_in[3];
    const float* g0  = (const float*)d_in[4];
    const float* be0 = (const float*)d_in[5];
    const float* W1  = (const float*)d_in[6];
    const float* b1  = (const float*)d_in[7];
    const float* g1  = (const float*)d_in[8];
    const float* be1 = (const float*)d_in[9];
    const float* fW0 = (const float*)d_in[10];
    const float* fb0 = (const float*)d_in[11];
    const float* fW1 = (const float*)d_in[12];
    const float* fb1 = (const float*)d_in[13];
    float* out = (float*)d_out;

    float *deg, *h1, *h2;
    __nv_bfloat16 *xh, *xl, *a1h, *a1l, *a2h, *a2l;
    __nv_bfloat16 *wth0, *wtl0, *wth1, *wtl1, *wth2, *wtl2, *wth3, *wtl3;
    cudaGetSymbolAddress((void**)&deg, g_deg);
    cudaGetSymbolAddress((void**)&h1, g_h1);
    cudaGetSymbolAddress((void**)&h2, g_h2);
    cudaGetSymbolAddress((void**)&xh, g_xh);
    cudaGetSymbolAddress((void**)&xl, g_xl);
    cudaGetSymbolAddress((void**)&a1h, g_a1h);
    cudaGetSymbolAddress((void**)&a1l, g_a1l);
    cudaGetSymbolAddress((void**)&a2h, g_a2h);
    cudaGetSymbolAddress((void**)&a2l, g_a2l);
    cudaGetSymbolAddress((void**)&wth0, g_wth0);
    cudaGetSymbolAddress((void**)&wtl0, g_wtl0);
    cudaGetSymbolAddress((void**)&wth1, g_wth1);
    cudaGetSymbolAddress((void**)&wtl1, g_wtl1);
    cudaGetSymbolAddress((void**)&wth2, g_wth2);
    cudaGetSymbolAddress((void**)&wtl2, g_wtl2);
    cudaGetSymbolAddress((void**)&wth3, g_wth3);
    cudaGetSymbolAddress((void**)&wtl3, g_wtl3);

    cudaFuncSetAttribute(gemm_mma, cudaFuncAttributeMaxDynamicSharedMemorySize, SMEM_DYN);
    cudaFuncSetAttribute(fused_fc, cudaFuncAttributeMaxDynamicSharedMemorySize, SMEM_DYN);

    const int M = N_NODES;
    dim3 tb(32, 8);

    // weight prep (one launch) + input split (deg-independent)
    TSeg s0 = {W0, wth0, wtl0, 500, 512, 256, 256};
    TSeg s1 = {W1, wth1, wtl1, 256, 256, 256, 256};
    TSeg s2 = {fW0, wth2, wtl2, 256, 256, 128, 128};
    TSeg s3 = {fW1, wth3, wtl3, 128, 128, 40, 128};
    transpose_split4<<<dim3(16, 8, 4), tb>>>(s0, s1, s2, s3);
    split_act<<<(M * 128 + 255) / 256, 256>>>(x, xh, xl, M, 500, 512);

    // degree: streaming memset + dedup scatter
    init_kernel<<<(BITMAP_WORDS / 4 + 256) / 256, 256>>>((const unsigned int*)ei);
    deg_kernel<<<(N_EDGES / 2 + 255) / 256, 256>>>(ei);

    // conv0: h1 = relu(deg .* (x@W0) + b0), stats fused; apply folds deg for conv1
    gemm_mma<<<dim3(2, 79), 256, SMEM_DYN>>>(xh, xl, wth0, wtl0, b0, deg, h1, M, 512, 256);
    bn_finalize<<<1, 256>>>(79, 256, M);
    bn_apply_split<<<(M * 64 + 255) / 256, 256>>>(h1, g0, be0, deg, a1h, a1l, M, 256);

    // conv1: h2 = relu(a1 @ W1 + b1), stats fused
    gemm_mma<<<dim3(2, 79), 256, SMEM_DYN>>>(a1h, a1l, wth1, wtl1, b1, nullptr, h2, M, 256, 256);
    bn_finalize<<<1, 256>>>(79, 256, M);
    bn_apply_split<<<(M * 64 + 255) / 256, 256>>>(h2, g1, be1, nullptr, a2h, a2l, M, 256);

    // fused fc0+fc1 -> out [10000][40]
    fused_fc<<<dim3(1, 79), 256, SMEM_DYN>>>(a2h, a2l, wth2, wtl2, fb0, wth3, wtl3, fb1, out, M);
}

// round 9
// speedup vs baseline: 1.4410x; 1.2823x over previous
#include <cuda_runtime.h>
#include <cuda_bf16.h>
#include <cstdint>

#define N_NODES 10000
#define N_EDGES 320000
#define M_PAD 10176           // 53 * 192
#define NBY 53
#define TOTAL_CTAS 106        // 2 * 53
#define HSIZE (1 << 20)
#define HMASK (HSIZE - 1)

// ---------------- scratch (static device globals; no allocation) ----------------
__device__ unsigned int g_htab[HSIZE];     // re-initialized to 0xFF each call
__device__ float g_deg[N_NODES];
__device__ float g_h1[N_NODES * 256];
__device__ float g_h2[N_NODES * 256];
__device__ float g_psum[NBY * 256];
__device__ float g_psum2[NBY * 256];
__device__ float g_mean[256];
__device__ float g_rstd[256];
__device__ unsigned int g_ctr;
__device__ int g_is64;
// bf16-split activations, zero-padded rows to M_PAD (padding stays zero forever)
__device__ __nv_bfloat16 g_xh[M_PAD * 512];
__device__ __nv_bfloat16 g_xl[M_PAD * 512];
__device__ __nv_bfloat16 g_a1h[M_PAD * 256];
__device__ __nv_bfloat16 g_a1l[M_PAD * 256];
__device__ __nv_bfloat16 g_a2h[M_PAD * 256];
__device__ __nv_bfloat16 g_a2l[M_PAD * 256];
// transposed + bf16-split weights, zero-padded: [Npad][KP]
__device__ __nv_bfloat16 g_wth0[256 * 512];
__device__ __nv_bfloat16 g_wtl0[256 * 512];
__device__ __nv_bfloat16 g_wth1[256 * 256];
__device__ __nv_bfloat16 g_wtl1[256 * 256];
__device__ __nv_bfloat16 g_wth2[128 * 256];
__device__ __nv_bfloat16 g_wtl2[128 * 256];
__device__ __nv_bfloat16 g_wth3[128 * 128];
__device__ __nv_bfloat16 g_wtl3[128 * 128];

// ---------------- helpers ----------------
__device__ __forceinline__ uint32_t s2u(const void* p) {
    uint32_t a;
    asm("{ .reg .u64 t; cvta.to.shared.u64 t, %1; cvt.u32.u64 %0, t; }" : "=r"(a) : "l"(p));
    return a;
}

__device__ __forceinline__ void bsplit(float v, unsigned short& h, unsigned short& l) {
    __nv_bfloat16 hb = __float2bfloat16(v);
    float r = v - __bfloat162float(hb);
    __nv_bfloat16 lb = __float2bfloat16(r);
    h = __bfloat16_as_ushort(hb);
    l = __bfloat16_as_ushort(lb);
}

#define LDX4(r, addr) \
    asm volatile("ldmatrix.sync.aligned.m8n8.x4.shared.b16 {%0,%1,%2,%3}, [%4];" \
                 : "=r"((r)[0]), "=r"((r)[1]), "=r"((r)[2]), "=r"((r)[3]) : "r"(addr))

#define MMA(d, a, b0, b1) \
    asm volatile("mma.sync.aligned.m16n8k16.row.col.f32.bf16.bf16.f32 " \
                 "{%0,%1,%2,%3}, {%4,%5,%6,%7}, {%8,%9}, {%0,%1,%2,%3};" \
                 : "+f"((d)[0]), "+f"((d)[1]), "+f"((d)[2]), "+f"((d)[3]) \
                 : "r"((a)[0]), "r"((a)[1]), "r"((a)[2]), "r"((a)[3]), "r"(b0), "r"(b1))

#define CP_ASYNC16(dst, src) \
    asm volatile("cp.async.cg.shared.global [%0], [%1], 16;" :: "r"(dst), "l"(src))

// ---------------- prep: transposes + input split + hash init + deg init + detect --------
// block ranges: [0,240) transpose, [240,5240) split_act, [5240,6264) htab init, [6264,6304) deg
__global__ void prep_kernel(const float* __restrict__ W0, const float* __restrict__ W1,
                            const float* __restrict__ fW0, const float* __restrict__ fW1,
                            const float* __restrict__ x, const unsigned int* __restrict__ eiw) {
    int b = blockIdx.x, tid = threadIdx.x;
    if (b < 240) {
        const float* W;
        __nv_bfloat16 *th, *tl;
        int K, KP, N, nk, lb;
        if (b < 128)      { W = W0;  th = g_wth0; tl = g_wtl0; K = 500; KP = 512; N = 256; nk = 16; lb = b; }
        else if (b < 192) { W = W1;  th = g_wth1; tl = g_wtl1; K = 256; KP = 256; N = 256; nk = 8;  lb = b - 128; }
        else if (b < 224) { W = fW0; th = g_wth2; tl = g_wtl2; K = 256; KP = 256; N = 128; nk = 8;  lb = b - 192; }
        else              { W = fW1; th = g_wth3; tl = g_wtl3; K = 128; KP = 128; N = 40;  nk = 4;  lb = b - 224; }
        int k0 = (lb % nk) * 32, n0 = (lb / nk) * 32;
        __shared__ float t[32][33];
        int tx = tid & 31, ty = tid >> 5;
        for (int dy = ty; dy < 32; dy += 8) {
            int k = k0 + dy, n = n0 + tx;
            t[dy][tx] = (k < K && n < N) ? W[(size_t)k * N + n] : 0.f;
        }
        __syncthreads();
        for (int dy = ty; dy < 32; dy += 8) {
            int n = n0 + dy, k = k0 + tx;
            unsigned short h, l;
            bsplit(t[tx][dy], h, l);
            th[(size_t)n * KP + k] = __ushort_as_bfloat16(h);
            tl[(size_t)n * KP + k] = __ushort_as_bfloat16(l);
        }
    } else if (b < 5240) {
        int idx = (b - 240) * 256 + tid;  // over 10000*128 4-col groups
        int row = idx >> 7, c4 = (idx & 127) * 4;
        const int K = 500, KP = 512;
        float v[4] = {0.f, 0.f, 0.f, 0.f};
        if (c4 + 3 < K) {
            float4 f = *(const float4*)&x[(size_t)row * K + c4];
            v[0] = f.x; v[1] = f.y; v[2] = f.z; v[3] = f.w;
        } else {
#pragma unroll
            for (int j = 0; j < 4; j++)
                if (c4 + j < K) v[j] = x[(size_t)row * K + c4 + j];
        }
        unsigned short h[4], l[4];
#pragma unroll
        for (int j = 0; j < 4; j++) bsplit(v[j], h[j], l[j]);
        *(uint2*)&g_xh[(size_t)row * KP + c4] =
            make_uint2((uint32_t)h[0] | ((uint32_t)h[1] << 16), (uint32_t)h[2] | ((uint32_t)h[3] << 16));
        *(uint2*)&g_xl[(size_t)row * KP + c4] =
            make_uint2((uint32_t)l[0] | ((uint32_t)l[1] << 16), (uint32_t)l[2] | ((uint32_t)l[3] << 16));
    } else if (b < 6264) {
        int i = (b - 5240) * 256 + tid;   // uint4 groups over HSIZE words
        uint4 ff = {~0u, ~0u, ~0u, ~0u};
        *(uint4*)&g_htab[i * 4] = ff;
    } else {
        int lb = b - 6264;
        int i = lb * 256 + tid;
        if (i < N_NODES) g_deg[i] = 1.0f;
        if (lb == 0 && tid < 32) {
            unsigned bad = (eiw[2 * tid + 1] != 0u) ? 1u : 0u;
            unsigned m = __ballot_sync(0xffffffffu, bad);
            if (tid == 0) g_is64 = (m == 0) ? 1 : 0;
        }
    }
}

// ---------------- degree with hash-set dedup, 2 edges/thread ----------------
__global__ void deg_kernel(const void* __restrict__ ei_raw) {
    int t = blockIdx.x * blockDim.x + threadIdx.x;
    const int half = N_EDGES / 2;
    if (t >= half) return;
    const int is64 = g_is64;
#pragma unroll
    for (int u = 0; u < 2; u++) {
        int e = t + u * half;
        int s, d;
        if (is64) {
            const long long* p = (const long long*)ei_raw;
            s = (int)p[e];
            d = (int)p[e + N_EDGES];
        } else {
            const int* p = (const int*)ei_raw;
            s = p[e];
            d = p[e + N_EDGES];
        }
        if ((unsigned)s >= N_NODES || (unsigned)d >= N_NODES) continue;
        if (s == d) continue;  // diagonal already 1 via eye()
        unsigned int k = (unsigned int)s * (unsigned int)N_NODES + (unsigned int)d;
        unsigned int h = (k * 2654435761u) >> 12;  // top 20 bits
        for (unsigned int j = 0;; j++) {
            unsigned int slot = (h + j) & HMASK;
            unsigned int old = atomicCAS(&g_htab[slot], 0xFFFFFFFFu, k);
            if (old == 0xFFFFFFFFu) { atomicAdd(&g_deg[s], 1.0f); break; }
            if (old == k) break;
        }
    }
}

// ---------------- conv GEMM: BM=192, BN=128, BK=32, 8 warps (4m x 2n), warp 48x64 --------
// cp.async 3-stage pipeline; epilogue relu(rs*acc+bias) + fused BN stats + last-CTA finalize.
#define ROWB 80
#define GA_H 0
#define GA_L 15360
#define GB_H 30720
#define GB_L 40960
#define GBUF 51200
#define GSMEM (3 * GBUF + 1024)

__global__ void __launch_bounds__(256, 1)
gemm192(const __nv_bfloat16* __restrict__ Ah, const __nv_bfloat16* __restrict__ Al,
        const __nv_bfloat16* __restrict__ Bh, const __nv_bfloat16* __restrict__ Bl,
        const float* __restrict__ bias, const float* __restrict__ rs,
        float* __restrict__ Cf, int M, int Kpad) {
    extern __shared__ char smraw[];
    uint32_t raw = s2u(smraw);
    uint32_t sbase = (raw + 1023u) & ~1023u;
    char* sb = smraw + (sbase - raw);

    const int tid = threadIdx.x, lane = tid & 31, wid = tid >> 5;
    const int row0 = blockIdx.y * 192, col0 = blockIdx.x * 128;
    const int wm = (wid >> 1) * 48, wn = (wid & 1) * 64;
    const int nch = Kpad >> 5;
    const int Ncols = 256;

    float acc[3][8][4];
#pragma unroll
    for (int i = 0; i < 3; i++)
#pragma unroll
        for (int j = 0; j < 8; j++)
#pragma unroll
            for (int c = 0; c < 4; c++) acc[i][j][c] = 0.f;

    const uint32_t a_lo = (uint32_t)((lane & 15) * ROWB + ((lane >> 4) & 1) * 16);
    const uint32_t b_lo = (uint32_t)((lane & 7) * ROWB + ((lane & 16) ? 8 * ROWB : 0) +
                                     ((lane & 8) ? 16 : 0));

    auto prefetch = [&](int ch) {
        const uint32_t bu = sbase + (ch % 3) * GBUF;
        const int k0 = ch << 5;
#pragma unroll
        for (int t = 0; t < 3; t++) {   // A: 192 rows x 4 x 16B
            int idx = tid + t * 256;
            int r = idx >> 2, q = idx & 3;
            size_t ao = (size_t)(row0 + r) * Kpad + k0 + q * 8;
            uint32_t so = (uint32_t)(r * ROWB + q * 16);
            CP_ASYNC16(bu + GA_H + so, (const void*)(Ah + ao));
            CP_ASYNC16(bu + GA_L + so, (const void*)(Al + ao));
        }
#pragma unroll
        for (int t = 0; t < 2; t++) {   // B: 128 rows x 4 x 16B
            int idx = tid + t * 256;
            int r = idx >> 2, q = idx & 3;
            size_t bo = (size_t)(col0 + r) * Kpad + k0 + q * 8;
            uint32_t so = (uint32_t)(r * ROWB + q * 16);
            CP_ASYNC16(bu + GB_H + so, (const void*)(Bh + bo));
            CP_ASYNC16(bu + GB_L + so, (const void*)(Bl + bo));
        }
        asm volatile("cp.async.commit_group;" ::: "memory");
    };

    prefetch(0);
    prefetch(1);

    for (int ch = 0; ch < nch; ch++) {
        if (ch + 1 < nch) { asm volatile("cp.async.wait_group 1;" ::: "memory"); }
        else              { asm volatile("cp.async.wait_group 0;" ::: "memory"); }
        __syncthreads();
        if (ch + 2 < nch) prefetch(ch + 2);

        const uint32_t bufu = sbase + (ch % 3) * GBUF;
#pragma unroll
        for (int ks = 0; ks < 2; ks++) {
            uint32_t ah[3][4], al[3][4];
#pragma unroll
            for (int mt = 0; mt < 3; mt++) {
                uint32_t ka = bufu + GA_H + (uint32_t)((wm + mt * 16) * ROWB) + a_lo + ks * 32;
                LDX4(ah[mt], ka);
                LDX4(al[mt], ka + (GA_L - GA_H));
            }
#pragma unroll
            for (int nt = 0; nt < 4; nt++) {
                uint32_t kb = bufu + GB_H + (uint32_t)((wn + nt * 16) * ROWB) + b_lo + ks * 32;
                uint32_t bh[4], bl[4];
                LDX4(bh, kb);
                LDX4(bl, kb + (GB_L - GB_H));
#pragma unroll
                for (int mt = 0; mt < 3; mt++) {
                    MMA(acc[mt][nt * 2 + 0], ah[mt], bh[0], bh[1]);
                    MMA(acc[mt][nt * 2 + 1], ah[mt], bh[2], bh[3]);
                    MMA(acc[mt][nt * 2 + 0], al[mt], bh[0], bh[1]);
                    MMA(acc[mt][nt * 2 + 1], al[mt], bh[2], bh[3]);
                    MMA(acc[mt][nt * 2 + 0], ah[mt], bl[0], bl[1]);
                    MMA(acc[mt][nt * 2 + 1], ah[mt], bl[2], bl[3]);
                }
            }
        }
        __syncthreads();
    }

    // epilogue: v = relu(rs*acc + bias); stores + fused column stats
    float ts[8][2], ts2[8][2];
#pragma unroll
    for (int j = 0; j < 8; j++) { ts[j][0] = ts[j][1] = ts2[j][0] = ts2[j][1] = 0.f; }
#pragma unroll
    for (int mi = 0; mi < 3; mi++) {
        int r0_ = row0 + wm + mi * 16 + (lane >> 2);
        bool ok0 = r0_ < M, ok1 = (r0_ + 8) < M;
        float d0 = 1.f, d1 = 1.f;
        if (rs) {
            if (ok0) d0 = rs[r0_];
            if (ok1) d1 = rs[r0_ + 8];
        }
#pragma unroll
        for (int n8 = 0; n8 < 8; n8++) {
            int gc = col0 + wn + n8 * 8 + (lane & 3) * 2;
            float bv0 = bias[gc], bv1 = bias[gc + 1];
            float v0 = d0 * acc[mi][n8][0] + bv0; v0 = v0 > 0.f ? v0 : 0.f;
            float v1 = d0 * acc[mi][n8][1] + bv1; v1 = v1 > 0.f ? v1 : 0.f;
            float v2 = d1 * acc[mi][n8][2] + bv0; v2 = v2 > 0.f ? v2 : 0.f;
            float v3 = d1 * acc[mi][n8][3] + bv1; v3 = v3 > 0.f ? v3 : 0.f;
            if (ok0) { ts[n8][0] += v0; ts2[n8][0] += v0 * v0;
                       ts[n8][1] += v1; ts2[n8][1] += v1 * v1; }
            if (ok1) { ts[n8][0] += v2; ts2[n8][0] += v2 * v2;
                       ts[n8][1] += v3; ts2[n8][1] += v3 * v3; }
            if (ok0) *(float2*)&Cf[(size_t)r0_ * Ncols + gc] = make_float2(v0, v1);
            if (ok1) *(float2*)&Cf[(size_t)(r0_ + 8) * Ncols + gc] = make_float2(v2, v3);
        }
    }

    // warp-level stat reduce (lanes differing in bits 2..4 hold different rows)
#pragma unroll
    for (int n8 = 0; n8 < 8; n8++)
#pragma unroll
        for (int k = 0; k < 2; k++) {
#pragma unroll
            for (int off = 4; off < 32; off <<= 1) {
                ts[n8][k] += __shfl_xor_sync(0xffffffffu, ts[n8][k], off);
                ts2[n8][k] += __shfl_xor_sync(0xffffffffu, ts2[n8][k], off);
            }
        }
    float* sS = (float*)sb;
    float* sS2 = sS + 8 * 64;
    __syncthreads();
    if (lane < 4) {
#pragma unroll
        for (int n8 = 0; n8 < 8; n8++) {
            int cloc = n8 * 8 + lane * 2;
            sS[wid * 64 + cloc] = ts[n8][0];
            sS[wid * 64 + cloc + 1] = ts[n8][1];
            sS2[wid * 64 + cloc] = ts2[n8][0];
            sS2[wid * 64 + cloc + 1] = ts2[n8][1];
        }
    }
    __syncthreads();
    if (tid < 128) {
        int c = tid;
        int half = c >> 6, cloc = c & 63;
        float s = 0.f, s2 = 0.f;
#pragma unroll
        for (int w = 0; w < 4; w++) {
            s += sS[(half + 2 * w) * 64 + cloc];
            s2 += sS2[(half + 2 * w) * 64 + cloc];
        }
        g_psum[blockIdx.y * 256 + col0 + c] = s;
        g_psum2[blockIdx.y * 256 + col0 + c] = s2;
        __threadfence();
    }
    __syncthreads();

    // last CTA finalizes mean/rstd
    __shared__ int s_last;
    if (tid == 0) {
        unsigned int o = atomicAdd(&g_ctr, 1u);
        s_last = (o == TOTAL_CTAS - 1) ? 1 : 0;
    }
    __syncthreads();
    if (s_last) {
        __threadfence();
        int c = tid;  // 0..255
        float s = 0.f, s2 = 0.f;
        for (int b = 0; b < NBY; b++) { s += g_psum[b * 256 + c]; s2 += g_psum2[b * 256 + c]; }
        float m = s / (float)M;
        float var = s2 / (float)M - m * m;
        g_mean[c] = m;
        g_rstd[c] = rsqrtf(var + 1e-5f);
        if (tid == 0) g_ctr = 0;
    }
}

// -------- BN apply: fp32 in -> bf16 hi/lo split out (optional row-scale fold) --------
__global__ void bn_apply_split(const float* __restrict__ H, const float* __restrict__ g,
                               const float* __restrict__ b, const float* __restrict__ rs,
                               __nv_bfloat16* __restrict__ oh, __nv_bfloat16* __restrict__ ol,
                               int M, int N) {
    int idx = blockIdx.x * blockDim.x + threadIdx.x;
    int n4 = N >> 2;
    if (idx >= M * n4) return;
    int row = idx / n4, c4 = (idx % n4) * 4;
    float4 h = *(const float4*)&H[(size_t)row * N + c4];
    float r = rs ? rs[row] : 1.f;
    float* hp = &h.x;
    unsigned short hh[4], ll[4];
#pragma unroll
    for (int j = 0; j < 4; j++) {
        int c = c4 + j;
        float v = ((hp[j] - g_mean[c]) * g_rstd[c] * g[c] + b[c]) * r;
        bsplit(v, hh[j], ll[j]);
    }
    *(uint2*)&oh[(size_t)row * N + c4] =
        make_uint2((uint32_t)hh[0] | ((uint32_t)hh[1] << 16), (uint32_t)hh[2] | ((uint32_t)hh[3] << 16));
    *(uint2*)&ol[(size_t)row * N + c4] =
        make_uint2((uint32_t)ll[0] | ((uint32_t)ll[1] << 16), (uint32_t)ll[2] | ((uint32_t)ll[3] << 16));
}

// ---------------- fused fc0+fc1: out = relu(relu(a2@W2+b2) @ W3 + b3) ----------------
#define AH_OFF 0
#define AL_OFF 10240
#define BH_OFF 20480
#define BL_OFF 30720
#define BUF_SZ 40960
#define FSMEM (3 * BUF_SZ + 1024)

__global__ void __launch_bounds__(256, 1)
fused_fc(const __nv_bfloat16* __restrict__ Ah, const __nv_bfloat16* __restrict__ Al,
         const __nv_bfloat16* __restrict__ Bh, const __nv_bfloat16* __restrict__ Bl,
         const float* __restrict__ bias0,
         const __nv_bfloat16* __restrict__ W3h, const __nv_bfloat16* __restrict__ W3l,
         const float* __restrict__ bias1, float* __restrict__ Out, int M) {
    extern __shared__ char smraw[];
    uint32_t raw = s2u(smraw);
    uint32_t sbase = (raw + 1023u) & ~1023u;

    const int tid = threadIdx.x, lane = tid & 31, wid = tid >> 5;
    const int row0 = blockIdx.y * 128;
    const int wm = (wid >> 1) * 32, wn = (wid & 1) * 64;
    const int Kpad = 256, nch = 8;

    float acc[2][8][4];
#pragma unroll
    for (int i = 0; i < 2; i++)
#pragma unroll
        for (int j = 0; j < 8; j++)
#pragma unroll
            for (int c = 0; c < 4; c++) acc[i][j][c] = 0.f;

    const uint32_t a_lo = (uint32_t)((lane & 15) * ROWB + ((lane >> 4) & 1) * 16);
    const uint32_t b_lo = (uint32_t)((lane & 7) * ROWB + ((lane & 16) ? 8 * ROWB : 0) +
                                     ((lane & 8) ? 16 : 0));

    auto prefetch = [&](int ch) {
        const uint32_t bu = sbase + (ch % 3) * BUF_SZ;
        const int k0 = ch << 5;
#pragma unroll
        for (int t = 0; t < 2; t++) {
            int idx = tid + t * 256;
            int r = idx >> 2, q = idx & 3;
            size_t ao = (size_t)(row0 + r) * Kpad + k0 + q * 8;
            size_t bo = (size_t)r * Kpad + k0 + q * 8;
            uint32_t so = (uint32_t)(r * ROWB + q * 16);
            CP_ASYNC16(bu + AH_OFF + so, (const void*)(Ah + ao));
            CP_ASYNC16(bu + AL_OFF + so, (const void*)(Al + ao));
            CP_ASYNC16(bu + BH_OFF + so, (const void*)(Bh + bo));
            CP_ASYNC16(bu + BL_OFF + so, (const void*)(Bl + bo));
        }
        asm volatile("cp.async.commit_group;" ::: "memory");
    };

    prefetch(0);
    prefetch(1);

    for (int ch = 0; ch < nch; ch++) {
        if (ch + 1 < nch) { asm volatile("cp.async.wait_group 1;" ::: "memory"); }
        else              { asm volatile("cp.async.wait_group 0;" ::: "memory"); }
        __syncthreads();
        if (ch + 2 < nch) prefetch(ch + 2);

        const uint32_t bufu = sbase + (ch % 3) * BUF_SZ;
#pragma unroll
        for (int ks = 0; ks < 2; ks++) {
            uint32_t ka = bufu + AH_OFF + (uint32_t)(wm * ROWB) + a_lo + ks * 32;
            uint32_t ah0[4], ah1[4], al0[4], al1[4];
            LDX4(ah0, ka);
            LDX4(ah1, ka + 16 * ROWB);
            LDX4(al0, ka + (AL_OFF - AH_OFF));
            LDX4(al1, ka + (AL_OFF - AH_OFF) + 16 * ROWB);
#pragma unroll
            for (int nt = 0; nt < 4; nt++) {
                uint32_t kb = bufu + BH_OFF + (uint32_t)((wn + nt * 16) * ROWB) + b_lo + ks * 32;
                uint32_t bh[4], bl[4];
                LDX4(bh, kb);
                LDX4(bl, kb + (BL_OFF - BH_OFF));
                MMA(acc[0][nt * 2 + 0], ah0, bh[0], bh[1]);
                MMA(acc[1][nt * 2 + 0], ah1, bh[0], bh[1]);
                MMA(acc[0][nt * 2 + 1], ah0, bh[2], bh[3]);
                MMA(acc[1][nt * 2 + 1], ah1, bh[2], bh[3]);
                MMA(acc[0][nt * 2 + 0], al0, bh[0], bh[1]);
                MMA(acc[1][nt * 2 + 0], al1, bh[0], bh[1]);
                MMA(acc[0][nt * 2 + 1], al0, bh[2], bh[3]);
                MMA(acc[1][nt * 2 + 1], al1, bh[2], bh[3]);
                MMA(acc[0][nt * 2 + 0], ah0, bl[0], bl[1]);
                MMA(acc[1][nt * 2 + 0], ah1, bl[0], bl[1]);
                MMA(acc[0][nt * 2 + 1], ah0, bl[2], bl[3]);
                MMA(acc[1][nt * 2 + 1], ah1, bl[2], bl[3]);
            }
        }
        __syncthreads();
    }
    __syncthreads();  // stage-1 buffers now free

    const uint32_t SA = sbase;
    const uint32_t SB = sbase + 81920;

    // load fc1 weights (64 rows cover N=40 + zero pad) via cp.async
#pragma unroll
    for (int t = 0; t < 4; t++) {
        int idx = tid + t * 256;          // c(2b)|r(6b)|q(2b)
        int c = idx >> 8, r = (idx >> 2) & 63, q = idx & 3;
        size_t go = (size_t)r * 128 + c * 32 + q * 8;
        uint32_t so = SB + c * 10240 + (uint32_t)(r * ROWB + q * 16);
        CP_ASYNC16(so, (const void*)(W3h + go));
        CP_ASYNC16(so + 5120, (const void*)(W3l + go));
    }
    asm volatile("cp.async.commit_group;" ::: "memory");

    // stage-1 epilogue: relu(acc+bias0) -> bf16 split into SA (chunked layout)
    char* sac = smraw + (sbase - raw);
#pragma unroll
    for (int mi = 0; mi < 2; mi++) {
        int rl = wm + mi * 16 + (lane >> 2);
#pragma unroll
        for (int n8 = 0; n8 < 8; n8++) {
            int cl = wn + n8 * 8 + (lane & 3) * 2;
            float bv0 = bias0[cl], bv1 = bias0[cl + 1];
            float v0 = acc[mi][n8][0] + bv0; v0 = v0 > 0.f ? v0 : 0.f;
            float v1 = acc[mi][n8][1] + bv1; v1 = v1 > 0.f ? v1 : 0.f;
            float v2 = acc[mi][n8][2] + bv0; v2 = v2 > 0.f ? v2 : 0.f;
            float v3 = acc[mi][n8][3] + bv1; v3 = v3 > 0.f ? v3 : 0.f;
            unsigned short h0, h1, h2, h3, l0, l1, l2, l3;
            bsplit(v0, h0, l0); bsplit(v1, h1, l1);
            bsplit(v2, h2, l2); bsplit(v3, h3, l3);
            uint32_t off = (uint32_t)((cl >> 5) * 20480 + rl * ROWB + (cl & 31) * 2);
            *(uint32_t*)(sac + off) = (uint32_t)h0 | ((uint32_t)h1 << 16);
            *(uint32_t*)(sac + off + 10240) = (uint32_t)l0 | ((uint32_t)l1 << 16);
            uint32_t off8 = off + 8 * ROWB;
            *(uint32_t*)(sac + off8) = (uint32_t)h2 | ((uint32_t)h3 << 16);
            *(uint32_t*)(sac + off8 + 10240) = (uint32_t)l2 | ((uint32_t)l3 << 16);
        }
    }
    asm volatile("cp.async.wait_group 0;" ::: "memory");
    __syncthreads();

    // stage 2: each warp computes rows [wid*16, wid*16+16) x cols 0..63 (N=40 used)
    float acc2[8][4];
#pragma unroll
    for (int j = 0; j < 8; j++)
#pragma unroll
        for (int c = 0; c < 4; c++) acc2[j][c] = 0.f;

#pragma unroll
    for (int c = 0; c < 4; c++) {
#pragma unroll
        for (int ks = 0; ks < 2; ks++) {
            uint32_t ka = SA + c * 20480 + (uint32_t)(wid * 16 * ROWB) + a_lo + ks * 32;
            uint32_t ah[4], al[4];
            LDX4(ah, ka);
            LDX4(al, ka + 10240);
#pragma unroll
            for (int nt = 0; nt < 4; nt++) {
                uint32_t kb = SB + c * 10240 + (uint32_t)(nt * 16 * ROWB) + b_lo + ks * 32;
                uint32_t bh[4], bl[4];
                LDX4(bh, kb);
                LDX4(bl, kb + 5120);
                MMA(acc2[nt * 2 + 0], ah, bh[0], bh[1]);
                MMA(acc2[nt * 2 + 1], ah, bh[2], bh[3]);
                MMA(acc2[nt * 2 + 0], al, bh[0], bh[1]);
                MMA(acc2[nt * 2 + 1], al, bh[2], bh[3]);
                MMA(acc2[nt * 2 + 0], ah, bl[0], bl[1]);
                MMA(acc2[nt * 2 + 1], ah, bl[2], bl[3]);
            }
        }
    }

    // stage-2 epilogue: relu(acc2 + bias1) -> Out [M][40]
#pragma unroll
    for (int nt = 0; nt < 4; nt++)
#pragma unroll
        for (int h = 0; h < 2; h++) {
            int gc = nt * 16 + h * 8 + (lane & 3) * 2;
            if (gc >= 40) continue;
            float bv0 = bias1[gc], bv1 = bias1[gc + 1];
            int gr = row0 + wid * 16 + (lane >> 2);
            float* a2 = acc2[nt * 2 + h];
            if (gr < M) {
                float v0 = a2[0] + bv0; v0 = v0 > 0.f ? v0 : 0.f;
                float v1 = a2[1] + bv1; v1 = v1 > 0.f ? v1 : 0.f;
                *(float2*)&Out[(size_t)gr * 40 + gc] = make_float2(v0, v1);
            }
            if (gr + 8 < M) {
                float v2 = a2[2] + bv0; v2 = v2 > 0.f ? v2 : 0.f;
                float v3 = a2[3] + bv1; v3 = v3 > 0.f ? v3 : 0.f;
                *(float2*)&Out[(size_t)(gr + 8) * 40 + gc] = make_float2(v2, v3);
            }
        }
}

// ---------------- launch ----------------
extern "C" void kernel_launch(void* const* d_in, const int* in_sizes, int n_in,
                              void* d_out, int out_size) {
    const float* x   = (const float*)d_in[0];
    const void*  ei  = d_in[1];
    const float* W0  = (const float*)d_in[2];
    const float* b0  = (const float*)d_in[3];
    const float* g0  = (const float*)d_in[4];
    const float* be0 = (const float*)d_in[5];
    const float* W1  = (const float*)d_in[6];
    const float* b1  = (const float*)d_in[7];
    const float* g1  = (const float*)d_in[8];
    const float* be1 = (const float*)d_in[9];
    const float* fW0 = (const float*)d_in[10];
    const float* fb0 = (const float*)d_in[11];
    const float* fW1 = (const float*)d_in[12];
    const float* fb1 = (const float*)d_in[13];
    float* out = (float*)d_out;

    float *deg, *h1, *h2;
    __nv_bfloat16 *xh, *xl, *a1h, *a1l, *a2h, *a2l;
    __nv_bfloat16 *wth0, *wtl0, *wth1, *wtl1, *wth2, *wtl2, *wth3, *wtl3;
    cudaGetSymbolAddress((void**)&deg, g_deg);
    cudaGetSymbolAddress((void**)&h1, g_h1);
    cudaGetSymbolAddress((void**)&h2, g_h2);
    cudaGetSymbolAddress((void**)&xh, g_xh);
    cudaGetSymbolAddress((void**)&xl, g_xl);
    cudaGetSymbolAddress((void**)&a1h, g_a1h);
    cudaGetSymbolAddress((void**)&a1l, g_a1l);
    cudaGetSymbolAddress((void**)&a2h, g_a2h);
    cudaGetSymbolAddress((void**)&a2l, g_a2l);
    cudaGetSymbolAddress((void**)&wth0, g_wth0);
    cudaGetSymbolAddress((void**)&wtl0, g_wtl0);
    cudaGetSymbolAddress((void**)&wth1, g_wth1);
    cudaGetSymbolAddress((void**)&wtl1, g_wtl1);
    cudaGetSymbolAddress((void**)&wth2, g_wth2);
    cudaGetSymbolAddress((void**)&wtl2, g_wtl2);
    cudaGetSymbolAddress((void**)&wth3, g_wth3);
    cudaGetSymbolAddress((void**)&wtl3, g_wtl3);

    cudaFuncSetAttribute(gemm192, cudaFuncAttributeMaxDynamicSharedMemorySize, GSMEM);
    cudaFuncSetAttribute(fused_fc, cudaFuncAttributeMaxDynamicSharedMemorySize, FSMEM);

    const int M = N_NODES;

    // prep: weight transposes + input split + hash init + deg init + dtype detect
    prep_kernel<<<6304, 256>>>(W0, W1, fW0, fW1, x, (const unsigned int*)ei);

    // degree via hash-set dedup
    deg_kernel<<<(N_EDGES / 2 + 255) / 256, 256>>>(ei);

    // conv0: h1 = relu(deg .* (x@W0) + b0), stats + finalize fused
    gemm192<<<dim3(2, NBY), 256, GSMEM>>>(xh, xl, wth0, wtl0, b0, deg, h1, M, 512);
    bn_apply_split<<<(M * 64 + 255) / 256, 256>>>(h1, g0, be0, deg, a1h, a1l, M, 256);

    // conv1: h2 = relu(a1 @ W1 + b1), stats + finalize fused
    gemm192<<<dim3(2, NBY), 256, GSMEM>>>(a1h, a1l, wth1, wtl1, b1, nullptr, h2, M, 256);
    bn_apply_split<<<(M * 64 + 255) / 256, 256>>>(h2, g1, be1, nullptr, a2h, a2l, M, 256);

    // fused fc0+fc1 -> out [10000][40]
    fused_fc<<<dim3(1, 79), 256, FSMEM>>>(a2h, a2l, wth2, wtl2, fb0, wth3, wtl3, fb1, out, M);
}